// round 4
// baseline (speedup 1.0000x reference)
#include <cuda_runtime.h>
#include <cstdint>

// ---------------------------------------------------------------------------
// Problem constants
// ---------------------------------------------------------------------------
#define NB    32
#define IMGW  224
#define HPIX  (IMGW*IMGW)
#define ED    96
#define KDIM  1200               // 3 * 25 * 16 folded patch size
#define KPAD  1216               // padded to multiple of 32
#define BK    32
#define NKT   (KPAD/BK)          // 38
#define MDIM  (NB*16*64)         // 32768 output patches
#define PI_F  3.14159265358979323846f
#define SPAD  36                 // smem row pitch in floats

// Scratch (device globals)
__device__ float  g_w2r[20*96*96];        // w2 reordered [ij][c1][c2]
__device__ float  g_Wt[ED*KPAD];          // folded weight transposed [c2][KPAD]
__device__ float  g_beff[ED];             // folded bias
__device__ float  g_r[NB*400];            // per-batch radius table
__device__ float2 g_cs[1024];             // (cos,sin) per azimuth

__device__ __forceinline__ float to_tf32(float v) {
    float r; asm("cvt.rna.tf32.f32 %0, %1;" : "=f"(r) : "f"(v)); return r;
}

// m16n8k8 tf32 mma (row.col), fp32 accum
__device__ __forceinline__ void mma_tf32(float* c, const float* a, const float* b) {
    asm volatile(
        "mma.sync.aligned.m16n8k8.row.col.f32.tf32.tf32.f32 "
        "{%0,%1,%2,%3}, {%4,%5,%6,%7}, {%8,%9}, {%0,%1,%2,%3};"
        : "+f"(c[0]), "+f"(c[1]), "+f"(c[2]), "+f"(c[3])
        : "r"(__float_as_uint(a[0])), "r"(__float_as_uint(a[1])),
          "r"(__float_as_uint(a[2])), "r"(__float_as_uint(a[3])),
          "r"(__float_as_uint(b[0])), "r"(__float_as_uint(b[1])));
}

// ---------------------------------------------------------------------------
// Prep 1: reorder w2 [c2][c1][i][j] -> w2r [ij][c1][c2]
// ---------------------------------------------------------------------------
__global__ void w2r_kernel(const float* __restrict__ w2, float* __restrict__ w2r) {
    int idx = blockIdx.x * blockDim.x + threadIdx.x;
    if (idx >= 20*96*96) return;
    int ij  = idx / (96*96);
    int rem = idx - ij*96*96;
    int c1  = rem / 96;
    int c2  = rem - c1*96;
    int i = ij >> 2, j = ij & 3;
    w2r[idx] = w2[((c2*96 + c1)*5 + i)*4 + j];
}

// ---------------------------------------------------------------------------
// Prep 2: fold weights -> Wt[c2][KPAD] (transposed, tf32-rounded; pads zeroed)
// ---------------------------------------------------------------------------
__global__ void weff_kernel(const float* __restrict__ w1,
                            const float* __restrict__ w2r,
                            float* __restrict__ Wt) {
    int k  = blockIdx.x;        // 0..KPAD-1
    int c2 = threadIdx.x;       // 0..95
    if (k >= KDIM) { Wt[(size_t)c2*KPAD + k] = 0.f; return; }
    int c   = k / 400;
    int rem = k - c*400;
    int r = rem >> 4;
    int a = rem & 15;
    int i = r / 5, p = r - i*5;
    int j = a >> 2, q = a & 3;

    __shared__ float w1col[96];
    w1col[c2] = w1[((c2*3 + c)*5 + p)*4 + q];
    __syncthreads();

    const float* wp = w2r + (i*4 + j)*96*96 + c2;
    float s = 0.f;
#pragma unroll 8
    for (int c1 = 0; c1 < 96; c1++) s += w1col[c1] * wp[c1*96];
    Wt[(size_t)c2*KPAD + k] = to_tf32(s);
}

// ---------------------------------------------------------------------------
// Prep 3: folded bias + theta_max output
// ---------------------------------------------------------------------------
__global__ void prep_kernel(const float* __restrict__ b1, const float* __restrict__ b2,
                            const float* __restrict__ w2r, float* __restrict__ beff,
                            float* __restrict__ outTheta, int nTheta) {
    int c2 = threadIdx.x;   // blockDim = 96
    float s = b2[c2];
    for (int c1 = 0; c1 < 96; c1++) {
        float t = 0.f;
#pragma unroll
        for (int ij = 0; ij < 20; ij++) t += w2r[ij*9216 + c1*96 + c2];
        s += b1[c1] * t;
    }
    beff[c2] = s;
    if (c2 < nTheta) outTheta[c2] = 1.5707963267948966f;   // pi/2
}

// ---------------------------------------------------------------------------
// Prep 4: radius table r[b][ir] and azimuth (cos,sin) table
// ---------------------------------------------------------------------------
__global__ void rcs_kernel(const float* __restrict__ dist,
                           float* __restrict__ rtab, float2* __restrict__ cs) {
    int idx = blockIdx.x * blockDim.x + threadIdx.x;
    if (idx < NB*400) {
        int b = idx / 400, ir = idx - b*400;
        const float* dp = dist + b*4;
        float c0 = 0.2f + dp[0], c1 = 0.2f + dp[1];
        float c2 = 0.2f + dp[2], c3 = 0.2f + dp[3];
        const float tm = PI_F * 0.5f;
        float th  = tm * (ir + 0.5f) * (1.0f/400.0f);
        float t2  = th*th;
        float pn  = th * (c0 + t2*(c1 + t2*(c2 + t2*c3)));
        float tm2 = tm*tm;
        float pd  = tm * (c0 + tm2*(c1 + tm2*(c2 + tm2*c3)));
        rtab[idx] = pn / pd * (IMGW * 0.5f);
    } else if (idx < NB*400 + 1024) {
        int ia = idx - NB*400;
        float phi = 2.0f*PI_F * (ia + 0.5f) * (1.0f/1024.0f);
        float sp, cp;
        __sincosf(phi, &sp, &cp);
        cs[ia] = make_float2(cp, sp);
    }
}

// ---------------------------------------------------------------------------
// Fused sample + tensor-core GEMM:
//   C[m][c2] = sum_k sample(m,k) * Wt[c2][k] + beff[c2]
// Block: 128 rows (patches), 256 threads (8 warps: 4 M x 2 N).
// Per K-tile: each thread's k = kt*32 + lane (fixed) -> decode once;
// 16 bilinear samples per thread (rows wid, wid+8, ..., wid+120).
// ---------------------------------------------------------------------------
__global__ __launch_bounds__(256, 2)
void fused_kernel(const float* __restrict__ x, const float* __restrict__ Bw,
                  const float* __restrict__ rtab_g, const float2* __restrict__ cs_g,
                  const float* __restrict__ bias, float* __restrict__ C) {
    __shared__ float  As[128*SPAD];   // 18.4 KB
    __shared__ float  Bs[96*SPAD];    // 13.8 KB
    __shared__ float2 cs_s[1024];     // 8 KB
    __shared__ float  rt_s[400];      // 1.6 KB

    int tid  = threadIdx.x;
    int wid  = tid >> 5, lane = tid & 31;
    int wm   = wid & 3;
    int wn   = wid >> 2;
    int g    = lane >> 2;
    int tg   = lane & 3;

    int m0 = blockIdx.x * 128;
    int b  = m0 >> 10;

    // load tables
    for (int i = tid; i < 1024; i += 256) cs_s[i] = cs_g[i];
    for (int i = tid; i < 400;  i += 256) rt_s[i] = rtab_g[b*400 + i];

    const float4* Bg = (const float4*)Bw;
    const float* xb3 = x + (size_t)b*3*HPIX;

    float acc[2][6][4];
#pragma unroll
    for (int mt = 0; mt < 2; mt++)
#pragma unroll
        for (int nt = 0; nt < 6; nt++)
#pragma unroll
            for (int q = 0; q < 4; q++) acc[mt][nt][q] = 0.f;

    // prologue: B tile 0 into registers
    float4 rb[3];
#pragma unroll
    for (int i = 0; i < 3; i++) {
        int e = i*256 + tid, r = e >> 3, c = e & 7;
        rb[i] = Bg[(size_t)r*(KPAD/4) + c];
    }

    // row decomposition for this thread's 16 sample rows (row = i*8 + wid)
    const float SCL = 111.5f / 112.0f;

    for (int kt = 0; kt < NKT; ++kt) {
        // decode this lane's k (fixed for the whole tile)
        int k  = kt*32 + lane;
        int c  = k / 400;
        int rem = k - c*400;
        int rr = rem >> 4;
        int aa = rem & 15;
        bool kvalid = (k < KDIM);
        const float* xb = xb3 + (size_t)c*HPIX;

        __syncthreads();   // previous tile's MMAs done reading smem (also covers table load at kt=0)

        // store B tile
#pragma unroll
        for (int i = 0; i < 3; i++) {
            int e = i*256 + tid, r = e >> 3, cq = e & 7;
            *(float4*)&Bs[r*SPAD + cq*4] = rb[i];
        }

        // sample 16 A values (rows i*8+wid, col = lane)
#pragma unroll
        for (int i = 0; i < 16; i++) {
            int m  = i*8 + wid;
            int mm = m0 + m;
            int pa = mm & 63;
            int pr = (mm >> 6) & 15;
            float v = 0.f;
            if (kvalid) {
                int ir = pr*25 + rr;
                int ia = pa*16 + aa;
                float rad = rt_s[ir];
                float2 cs = cs_s[ia];
                float gx = fmaf(rad*cs.y, SCL, 111.5f);
                float gy = fmaf(rad*cs.x, SCL, 111.5f);
                float x0f = floorf(gx), y0f = floorf(gy);
                float wx1 = gx - x0f, wx0 = 1.0f - wx1;
                float wy1 = gy - y0f, wy0 = 1.0f - wy1;
                int x0 = min(222, max(0, (int)x0f));
                int y0 = min(222, max(0, (int)y0f));
                const float* p = xb + y0*IMGW + x0;
                v = wx0*wy0*__ldg(p)        + wx1*wy0*__ldg(p + 1)
                  + wx0*wy1*__ldg(p + IMGW) + wx1*wy1*__ldg(p + IMGW + 1);
                v = to_tf32(v);
            }
            As[m*SPAD + lane] = v;
        }
        __syncthreads();

        // prefetch next B tile (overlaps MMAs)
        if (kt + 1 < NKT) {
            int ko = (kt + 1) * 8;
#pragma unroll
            for (int i = 0; i < 3; i++) {
                int e = i*256 + tid, r = e >> 3, cq = e & 7;
                rb[i] = Bg[(size_t)r*(KPAD/4) + ko + cq];
            }
        }

        // MMA over 4 k-steps of 8
#pragma unroll
        for (int ks = 0; ks < 4; ks++) {
            int kb = ks * 8;
            float af[2][4];
#pragma unroll
            for (int mt = 0; mt < 2; mt++) {
                int rbase = wm*32 + mt*16;
                af[mt][0] = As[(rbase + g    )*SPAD + kb + tg    ];
                af[mt][1] = As[(rbase + g + 8)*SPAD + kb + tg    ];
                af[mt][2] = As[(rbase + g    )*SPAD + kb + tg + 4];
                af[mt][3] = As[(rbase + g + 8)*SPAD + kb + tg + 4];
            }
            float bf[6][2];
#pragma unroll
            for (int nt = 0; nt < 6; nt++) {
                int n = wn*48 + nt*8 + g;
                bf[nt][0] = Bs[n*SPAD + kb + tg    ];
                bf[nt][1] = Bs[n*SPAD + kb + tg + 4];
            }
#pragma unroll
            for (int mt = 0; mt < 2; mt++)
#pragma unroll
                for (int nt = 0; nt < 6; nt++)
                    mma_tf32(acc[mt][nt], af[mt], bf[nt]);
        }
    }

    // epilogue
#pragma unroll
    for (int nt = 0; nt < 6; nt++) {
        int col = wn*48 + nt*8 + 2*tg;
        float2 bv = *(const float2*)(bias + col);
#pragma unroll
        for (int mt = 0; mt < 2; mt++) {
            int row = m0 + wm*32 + mt*16 + g;
            float2 v0 = { acc[mt][nt][0] + bv.x, acc[mt][nt][1] + bv.y };
            float2 v1 = { acc[mt][nt][2] + bv.x, acc[mt][nt][3] + bv.y };
            *(float2*)(C + (size_t)row*96 + col)       = v0;
            *(float2*)(C + (size_t)(row + 8)*96 + col) = v1;
        }
    }
}

// ---------------------------------------------------------------------------
// Launch
// ---------------------------------------------------------------------------
extern "C" void kernel_launch(void* const* d_in, const int* in_sizes, int n_in,
                              void* d_out, int out_size) {
    const float* x    = (const float*)d_in[0];
    const float* dist = (const float*)d_in[1];
    const float* w1   = (const float*)d_in[2];
    const float* b1   = (const float*)d_in[3];
    const float* w2   = (const float*)d_in[4];
    const float* b2   = (const float*)d_in[5];
    float* out = (float*)d_out;

    float *dW2r, *dWt, *dBeff, *dR;
    float2* dCS;
    cudaGetSymbolAddress((void**)&dW2r,  g_w2r);
    cudaGetSymbolAddress((void**)&dWt,   g_Wt);
    cudaGetSymbolAddress((void**)&dBeff, g_beff);
    cudaGetSymbolAddress((void**)&dR,    g_r);
    cudaGetSymbolAddress((void**)&dCS,   g_cs);

    int nT = MDIM * ED;
    int nTheta = (out_size > nT) ? (out_size - nT) : 0;

    w2r_kernel<<<(20*96*96 + 255)/256, 256>>>(w2, dW2r);
    rcs_kernel<<<(NB*400 + 1024 + 255)/256, 256>>>(dist, dR, dCS);
    weff_kernel<<<KPAD, 96>>>(w1, dW2r, dWt);
    prep_kernel<<<1, 96>>>(b1, b2, dW2r, dBeff, out + nT, nTheta);
    fused_kernel<<<MDIM/128, 256>>>(x, dWt, dR, dCS, dBeff, out);
}

// round 5
// speedup vs baseline: 1.6857x; 1.6857x over previous
#include <cuda_runtime.h>
#include <cstdint>

// ---------------------------------------------------------------------------
// Problem constants
// ---------------------------------------------------------------------------
#define NB    32
#define IMGW  224
#define HPIX  (IMGW*IMGW)
#define ED    96
#define KDIM  1200               // 3 * 25 * 16 folded patch size
#define KPAD  1216               // padded to multiple of 32 (zero tail)
#define BK    32                 // K-tile
#define NKT   (KPAD/BK)          // 38
#define MDIM  (NB*16*64)         // 32768 output patches
#define PI_F  3.14159265358979323846f
#define SPAD  36                 // smem row pitch in floats (32 + 4 pad)

// Scratch (device globals; no runtime allocation allowed)
__device__ float g_S[(size_t)MDIM * KPAD];    // sampled, patch-major [M][KPAD]
__device__ float g_w2r[20*96*96];             // w2 reordered [ij][c1][c2]
__device__ float g_Wt[ED*KPAD];               // folded weight TRANSPOSED [c2][KPAD]
__device__ float g_beff[ED];                  // folded bias

__device__ __forceinline__ float to_tf32(float v) {
    float r; asm("cvt.rna.tf32.f32 %0, %1;" : "=f"(r) : "f"(v)); return r;
}

// m16n8k8 tf32 mma (row.col), fp32 accum
__device__ __forceinline__ void mma_tf32(float* c, const float* a, const float* b) {
    asm volatile(
        "mma.sync.aligned.m16n8k8.row.col.f32.tf32.tf32.f32 "
        "{%0,%1,%2,%3}, {%4,%5,%6,%7}, {%8,%9}, {%0,%1,%2,%3};"
        : "+f"(c[0]), "+f"(c[1]), "+f"(c[2]), "+f"(c[3])
        : "r"(__float_as_uint(a[0])), "r"(__float_as_uint(a[1])),
          "r"(__float_as_uint(a[2])), "r"(__float_as_uint(a[3])),
          "r"(__float_as_uint(b[0])), "r"(__float_as_uint(b[1])));
}

// ---------------------------------------------------------------------------
// Prep 1: reorder w2 [c2][c1][i][j] -> w2r [ij][c1][c2]
// ---------------------------------------------------------------------------
__global__ void w2r_kernel(const float* __restrict__ w2, float* __restrict__ w2r) {
    int idx = blockIdx.x * blockDim.x + threadIdx.x;
    if (idx >= 20*96*96) return;
    int ij  = idx / (96*96);
    int rem = idx - ij*96*96;
    int c1  = rem / 96;
    int c2  = rem - c1*96;
    int i = ij >> 2, j = ij & 3;
    w2r[idx] = w2[((c2*96 + c1)*5 + i)*4 + j];
}

// ---------------------------------------------------------------------------
// Prep 2: fold weights -> Wt[c2][KPAD] (transposed, tf32-rounded; pads zeroed)
// ---------------------------------------------------------------------------
__global__ void weff_kernel(const float* __restrict__ w1,
                            const float* __restrict__ w2r,
                            float* __restrict__ Wt) {
    int k  = blockIdx.x;        // 0..KPAD-1
    int c2 = threadIdx.x;       // 0..95
    if (k >= KDIM) { Wt[(size_t)c2*KPAD + k] = 0.f; return; }
    int c   = k / 400;
    int rem = k - c*400;
    int r = rem >> 4;
    int a = rem & 15;
    int i = r / 5, p = r - i*5;
    int j = a >> 2, q = a & 3;

    __shared__ float w1col[96];
    w1col[c2] = w1[((c2*3 + c)*5 + p)*4 + q];
    __syncthreads();

    const float* wp = w2r + (i*4 + j)*96*96 + c2;
    float s = 0.f;
#pragma unroll 8
    for (int c1 = 0; c1 < 96; c1++) s += w1col[c1] * wp[c1*96];
    Wt[(size_t)c2*KPAD + k] = to_tf32(s);
}

// ---------------------------------------------------------------------------
// Prep 3 (PARALLEL): folded bias + theta_max.
// One block per c2 (96 blocks, 128 threads). Thread t<96 handles c1=t:
// reads 20 CONTIGUOUS floats of w2[c2][c1][:], multiplies by b1[c1],
// then block-reduces. Replaces the 74us single-block serial version.
// ---------------------------------------------------------------------------
__global__ void beff_kernel(const float* __restrict__ w2,
                            const float* __restrict__ b1,
                            const float* __restrict__ b2,
                            float* __restrict__ beff,
                            float* __restrict__ outTheta, int nTheta) {
    __shared__ float red[128];
    int c2 = blockIdx.x;
    int t  = threadIdx.x;

    float v = 0.f;
    if (t < 96) {
        const float* p = w2 + ((size_t)c2*96 + t)*20;
        float s = 0.f;
#pragma unroll
        for (int e = 0; e < 20; e++) s += p[e];
        v = s * b1[t];
    }
    red[t] = v;
    __syncthreads();
#pragma unroll
    for (int off = 64; off > 0; off >>= 1) {
        if (t < off) red[t] += red[t + off];
        __syncthreads();
    }
    if (t == 0) beff[c2] = red[0] + b2[c2];
    if (c2 == 0 && t < nTheta) outTheta[t] = 1.5707963267948966f;   // pi/2
}

// Prep 4: zero K pads (cols 1200..1215) of S
__global__ void zerotail_kernel(float* __restrict__ S) {
    int i = blockIdx.x * blockDim.x + threadIdx.x;
    if (i < MDIM*16)
        S[(size_t)(i >> 4)*KPAD + 1200 + (i & 15)] = 0.f;
}

// ---------------------------------------------------------------------------
// Sampling: polar grid + bilinear gather -> S[M][KPAD], tf32-rounded
// ---------------------------------------------------------------------------
__global__ __launch_bounds__(256) void sample_kernel(const float* __restrict__ x,
                                                     const float* __restrict__ dist,
                                                     float* __restrict__ S) {
    int t = blockIdx.x * blockDim.x + threadIdx.x;   // 32*400*1024 threads
    int ia = t & 1023;
    int ir = (t >> 10) % 400;
    int b  = t / (400*1024);

    const float* dp = dist + b*4;
    float c0 = 0.2f + dp[0], c1 = 0.2f + dp[1];
    float c2 = 0.2f + dp[2], c3 = 0.2f + dp[3];

    const float tm = PI_F * 0.5f;
    float th  = tm * (ir + 0.5f) * (1.0f/400.0f);
    float t2  = th*th;
    float pn  = th * (c0 + t2*(c1 + t2*(c2 + t2*c3)));
    float tm2 = tm*tm;
    float pd  = tm * (c0 + tm2*(c1 + tm2*(c2 + tm2*c3)));
    float r   = pn / pd * (IMGW * 0.5f);

    float phi = 2.0f*PI_F * (ia + 0.5f) * (1.0f/1024.0f);
    float sp, cp;
    __sincosf(phi, &sp, &cp);
    float xc = r*cp, yc = r*sp;

    float gx = (yc * (1.0f/112.0f) + 1.0f) * 0.5f * (IMGW - 1);
    float gy = (xc * (1.0f/112.0f) + 1.0f) * 0.5f * (IMGW - 1);

    float x0f = floorf(gx), y0f = floorf(gy);
    float wx1 = gx - x0f, wx0 = 1.0f - wx1;
    float wy1 = gy - y0f, wy0 = 1.0f - wy1;
    int x0 = min(222, max(0, (int)x0f));
    int y0 = min(222, max(0, (int)y0f));

    float w00 = wx0*wy0, w01 = wx1*wy0, w10 = wx0*wy1, w11 = wx1*wy1;

    const float* base = x + (size_t)b*3*HPIX + y0*IMGW + x0;
    int patch = b*1024 + (ir/25)*64 + (ia >> 4);
    float* so = S + (size_t)patch*KPAD + (ir % 25)*16 + (ia & 15);

#pragma unroll
    for (int ch = 0; ch < 3; ch++) {
        const float* p = base + ch*HPIX;
        float v = w00*__ldg(p)        + w01*__ldg(p + 1)
                + w10*__ldg(p + IMGW) + w11*__ldg(p + IMGW + 1);
        so[ch*400] = to_tf32(v);
    }
}

// ---------------------------------------------------------------------------
// Tensor-core GEMM via mma.sync tf32:
//   C[M][96] = S[M][KPAD] @ Wt[96][KPAD]^T + beff
// Block: BM=128 rows, 256 threads (8 warps: 4 along M x 2 along N).
// Warp tile: 32 x 48. BK=32, single-buffered smem with register prefetch.
// ---------------------------------------------------------------------------
__global__ __launch_bounds__(256, 2)
void gemm_mma(const float* __restrict__ A, const float* __restrict__ Bw,
              const float* __restrict__ bias, float* __restrict__ C) {
    __shared__ float As[128*SPAD];   // [row][k] pitch 36
    __shared__ float Bs[96*SPAD];    // [n][k]   pitch 36

    int tid = threadIdx.x;
    int wid = tid >> 5, lane = tid & 31;
    int wm = wid & 3;
    int wn = wid >> 2;
    int g  = lane >> 2;
    int tg = lane & 3;

    int m0 = blockIdx.x * 128;
    const float4* Ag = (const float4*)(A + (size_t)m0 * KPAD);
    const float4* Bg = (const float4*)Bw;

    float acc[2][6][4];
#pragma unroll
    for (int mt = 0; mt < 2; mt++)
#pragma unroll
        for (int nt = 0; nt < 6; nt++)
#pragma unroll
            for (int q = 0; q < 4; q++) acc[mt][nt][q] = 0.f;

    float4 ra[4], rb[3];
#pragma unroll
    for (int i = 0; i < 4; i++) {
        int e = i*256 + tid, r = e >> 3, c = e & 7;
        ra[i] = Ag[(size_t)r*(KPAD/4) + c];
    }
#pragma unroll
    for (int i = 0; i < 3; i++) {
        int e = i*256 + tid, r = e >> 3, c = e & 7;
        rb[i] = Bg[(size_t)r*(KPAD/4) + c];
    }

    for (int kt = 0; kt < NKT; ++kt) {
        __syncthreads();
#pragma unroll
        for (int i = 0; i < 4; i++) {
            int e = i*256 + tid, r = e >> 3, c = e & 7;
            *(float4*)&As[r*SPAD + c*4] = ra[i];
        }
#pragma unroll
        for (int i = 0; i < 3; i++) {
            int e = i*256 + tid, r = e >> 3, c = e & 7;
            *(float4*)&Bs[r*SPAD + c*4] = rb[i];
        }
        __syncthreads();

        if (kt + 1 < NKT) {
            int ko = (kt + 1) * 8;
#pragma unroll
            for (int i = 0; i < 4; i++) {
                int e = i*256 + tid, r = e >> 3, c = e & 7;
                ra[i] = Ag[(size_t)r*(KPAD/4) + ko + c];
            }
#pragma unroll
            for (int i = 0; i < 3; i++) {
                int e = i*256 + tid, r = e >> 3, c = e & 7;
                rb[i] = Bg[(size_t)r*(KPAD/4) + ko + c];
            }
        }

#pragma unroll
        for (int ks = 0; ks < 4; ks++) {
            int kb = ks * 8;
            float af[2][4];
#pragma unroll
            for (int mt = 0; mt < 2; mt++) {
                int rbase = wm*32 + mt*16;
                af[mt][0] = As[(rbase + g    )*SPAD + kb + tg    ];
                af[mt][1] = As[(rbase + g + 8)*SPAD + kb + tg    ];
                af[mt][2] = As[(rbase + g    )*SPAD + kb + tg + 4];
                af[mt][3] = As[(rbase + g + 8)*SPAD + kb + tg + 4];
            }
            float bf[6][2];
#pragma unroll
            for (int nt = 0; nt < 6; nt++) {
                int n = wn*48 + nt*8 + g;
                bf[nt][0] = Bs[n*SPAD + kb + tg    ];
                bf[nt][1] = Bs[n*SPAD + kb + tg + 4];
            }
#pragma unroll
            for (int mt = 0; mt < 2; mt++)
#pragma unroll
                for (int nt = 0; nt < 6; nt++)
                    mma_tf32(acc[mt][nt], af[mt], bf[nt]);
        }
    }

    // epilogue
#pragma unroll
    for (int nt = 0; nt < 6; nt++) {
        int col = wn*48 + nt*8 + 2*tg;
        float2 bv = *(const float2*)(bias + col);
#pragma unroll
        for (int mt = 0; mt < 2; mt++) {
            int row = m0 + wm*32 + mt*16 + g;
            float2 v0 = { acc[mt][nt][0] + bv.x, acc[mt][nt][1] + bv.y };
            float2 v1 = { acc[mt][nt][2] + bv.x, acc[mt][nt][3] + bv.y };
            *(float2*)(C + (size_t)row*96 + col)       = v0;
            *(float2*)(C + (size_t)(row + 8)*96 + col) = v1;
        }
    }
}

// ---------------------------------------------------------------------------
// Launch
// ---------------------------------------------------------------------------
extern "C" void kernel_launch(void* const* d_in, const int* in_sizes, int n_in,
                              void* d_out, int out_size) {
    const float* x    = (const float*)d_in[0];
    const float* dist = (const float*)d_in[1];
    const float* w1   = (const float*)d_in[2];
    const float* b1   = (const float*)d_in[3];
    const float* w2   = (const float*)d_in[4];
    const float* b2   = (const float*)d_in[5];
    float* out = (float*)d_out;

    float *dS, *dW2r, *dWt, *dBeff;
    cudaGetSymbolAddress((void**)&dS,    g_S);
    cudaGetSymbolAddress((void**)&dW2r,  g_w2r);
    cudaGetSymbolAddress((void**)&dWt,   g_Wt);
    cudaGetSymbolAddress((void**)&dBeff, g_beff);

    int nT = MDIM * ED;
    int nTheta = (out_size > nT) ? (out_size - nT) : 0;

    w2r_kernel<<<(20*96*96 + 255)/256, 256>>>(w2, dW2r);
    beff_kernel<<<96, 128>>>(w2, b1, b2, dBeff, out + nT, nTheta);
    weff_kernel<<<KPAD, 96>>>(w1, dW2r, dWt);
    zerotail_kernel<<<(MDIM*16 + 255)/256, 256>>>(dS);
    sample_kernel<<<(NB*400*1024)/256, 256>>>(x, dist, dS);
    gemm_mma<<<MDIM/128, 256>>>(dS, dWt, dBeff, out);
}

// round 6
// speedup vs baseline: 2.1160x; 1.2553x over previous
#include <cuda_runtime.h>
#include <cuda_fp16.h>
#include <cstdint>

// ---------------------------------------------------------------------------
// Problem constants
// ---------------------------------------------------------------------------
#define NB    32
#define IMGW  224
#define HPIX  (IMGW*IMGW)
#define ED    96
#define KDIM  1200               // 3 * 25 * 16 folded patch size
#define KPAD  1216               // padded to multiple of 32 (zero tail)
#define BK    32
#define NKT   (KPAD/BK)          // 38
#define MDIM  (NB*16*64)         // 32768 output patches
#define PI_F  3.14159265358979323846f
#define PADH  40                 // smem row pitch in halves (32 + 8 pad) -> conflict-free
#define STAGES 4

// Scratch (device globals)
__device__ __half g_S[(size_t)MDIM * KPAD];   // sampled fp16, patch-major [M][KPAD]
__device__ uint2  g_xh[(size_t)NB * HPIX];    // repacked image: 4x fp16 (c0,c1,c2,0)
__device__ __half g_Wt[(size_t)ED * KPAD];    // folded weight transposed [c2][KPAD], fp16
__device__ float  g_beff[ED];                 // folded bias (fp32)

// ---------------------------------------------------------------------------
// mma m16n8k16 fp16 -> fp32
// ---------------------------------------------------------------------------
__device__ __forceinline__ void mma_f16(float* c, uint32_t a0, uint32_t a1,
                                        uint32_t a2, uint32_t a3,
                                        uint32_t b0, uint32_t b1) {
    asm volatile(
        "mma.sync.aligned.m16n8k16.row.col.f32.f16.f16.f32 "
        "{%0,%1,%2,%3}, {%4,%5,%6,%7}, {%8,%9}, {%0,%1,%2,%3};"
        : "+f"(c[0]), "+f"(c[1]), "+f"(c[2]), "+f"(c[3])
        : "r"(a0), "r"(a1), "r"(a2), "r"(a3), "r"(b0), "r"(b1));
}

__device__ __forceinline__ uint32_t smem_u32(const void* p) {
    uint32_t a;
    asm("{ .reg .u64 t; cvta.to.shared.u64 t, %1; cvt.u32.u64 %0, t; }" : "=r"(a) : "l"(p));
    return a;
}
__device__ __forceinline__ void cp16(uint32_t dst, const void* src) {
    asm volatile("cp.async.ca.shared.global [%0], [%1], 16;" :: "r"(dst), "l"(src));
}
#define CP_COMMIT()  asm volatile("cp.async.commit_group;" ::: "memory")
#define CP_WAIT(n)   asm volatile("cp.async.wait_group %0;" :: "n"(n) : "memory")

// ---------------------------------------------------------------------------
// Prep (single kernel): fold weights -> Wt[c2][KPAD] fp16, beff, theta_max.
// One block per c2; w2[c2] slice (1920 f) + all of w1 (5760 f) in smem.
// ---------------------------------------------------------------------------
__global__ __launch_bounds__(256)
void prep_all(const float* __restrict__ w1, const float* __restrict__ w2,
              const float* __restrict__ b1, const float* __restrict__ b2,
              __half* __restrict__ Wt, float* __restrict__ beff,
              float* __restrict__ outTheta, int nTheta) {
    __shared__ float sw2[96*20];
    __shared__ float sw1[96*60];
    __shared__ float red[96];
    int c2 = blockIdx.x;
    int t  = threadIdx.x;

    for (int i = t; i < 96*20; i += 256) sw2[i] = w2[(size_t)c2*1920 + i];
    for (int i = t; i < 96*60; i += 256) sw1[i] = w1[i];
    __syncthreads();

    for (int k = t; k < KPAD; k += 256) {
        if (k >= KDIM) { Wt[(size_t)c2*KPAD + k] = __float2half(0.f); continue; }
        int c   = k / 400;
        int rem = k - c*400;
        int rr = rem >> 4, aa = rem & 15;
        int i = rr / 5, p = rr - i*5;
        int j = aa >> 2, q = aa & 3;
        int o2 = i*4 + j;
        int o1 = c*20 + p*4 + q;
        float s = 0.f;
#pragma unroll 8
        for (int c1 = 0; c1 < 96; c1++)
            s += sw2[c1*20 + o2] * sw1[c1*60 + o1];
        Wt[(size_t)c2*KPAD + k] = __float2half_rn(s);
    }

    if (t < 96) {
        float s = 0.f;
#pragma unroll
        for (int e = 0; e < 20; e++) s += sw2[t*20 + e];
        red[t] = s * b1[t];
    }
    __syncthreads();
    if (t == 0) {
        float s = b2[c2];
#pragma unroll 8
        for (int i = 0; i < 96; i++) s += red[i];
        beff[c2] = s;
    }
    if (c2 == 0 && t < nTheta) outTheta[t] = 1.5707963267948966f;   // pi/2
}

// ---------------------------------------------------------------------------
// Repack: planar fp32 image -> interleaved fp16x4 (c0,c1,c2,0); also zero S tail
// ---------------------------------------------------------------------------
__global__ __launch_bounds__(256)
void repack_kernel(const float* __restrict__ x, uint2* __restrict__ xh,
                   __half* __restrict__ S) {
    int idx = blockIdx.x * 256 + threadIdx.x;
    if (idx < NB*HPIX) {
        int b = idx / HPIX, p = idx - b*HPIX;
        const float* xb = x + (size_t)b*3*HPIX + p;
        float c0 = xb[0], c1 = xb[HPIX], c2 = xb[2*HPIX];
        __half2 lo = __floats2half2_rn(c0, c1);
        __half2 hi = __floats2half2_rn(c2, 0.f);
        uint2 v;
        v.x = *reinterpret_cast<uint32_t*>(&lo);
        v.y = *reinterpret_cast<uint32_t*>(&hi);
        xh[idx] = v;
    }
    if (idx < MDIM*8) {     // zero S cols 1200..1215 (8 uint writes per row)
        int row = idx >> 3, c = idx & 7;
        uint32_t* Su = reinterpret_cast<uint32_t*>(S);
        Su[((size_t)row*KPAD + 1200)/2 + c] = 0u;
    }
}

// ---------------------------------------------------------------------------
// Sampling: polar grid + bilinear gather (fp16x4 pixels) -> S fp16 [M][KPAD]
// 4 LDG.64 per sample point (all 3 channels per load).
// ---------------------------------------------------------------------------
__global__ __launch_bounds__(256)
void sample_kernel(const uint2* __restrict__ xh, const float* __restrict__ dist,
                   __half* __restrict__ S) {
    int t = blockIdx.x * blockDim.x + threadIdx.x;   // 32*400*1024 threads
    int ia = t & 1023;
    int ir = (t >> 10) % 400;
    int b  = t / (400*1024);

    const float* dp = dist + b*4;
    float c0 = 0.2f + dp[0], c1 = 0.2f + dp[1];
    float c2 = 0.2f + dp[2], c3 = 0.2f + dp[3];

    const float tm = PI_F * 0.5f;
    float th  = tm * (ir + 0.5f) * (1.0f/400.0f);
    float t2  = th*th;
    float pn  = th * (c0 + t2*(c1 + t2*(c2 + t2*c3)));
    float tm2 = tm*tm;
    float pd  = tm * (c0 + tm2*(c1 + tm2*(c2 + tm2*c3)));
    float r   = pn / pd * (IMGW * 0.5f);

    float phi = 2.0f*PI_F * (ia + 0.5f) * (1.0f/1024.0f);
    float sp, cp;
    __sincosf(phi, &sp, &cp);
    float xc = r*cp, yc = r*sp;

    float gx = (yc * (1.0f/112.0f) + 1.0f) * 0.5f * (IMGW - 1);
    float gy = (xc * (1.0f/112.0f) + 1.0f) * 0.5f * (IMGW - 1);

    float x0f = floorf(gx), y0f = floorf(gy);
    float wx1 = gx - x0f, wx0 = 1.0f - wx1;
    float wy1 = gy - y0f, wy0 = 1.0f - wy1;
    int x0 = min(222, max(0, (int)x0f));
    int y0 = min(222, max(0, (int)y0f));

    float w00 = wx0*wy0, w01 = wx1*wy0, w10 = wx0*wy1, w11 = wx1*wy1;

    const uint2* base = xh + (size_t)b*HPIX + y0*IMGW + x0;
    uint2 q00 = __ldg(base);
    uint2 q01 = __ldg(base + 1);
    uint2 q10 = __ldg(base + IMGW);
    uint2 q11 = __ldg(base + IMGW + 1);

    float2 a00 = __half22float2(*reinterpret_cast<__half2*>(&q00.x));
    float2 e00 = __half22float2(*reinterpret_cast<__half2*>(&q00.y));
    float2 a01 = __half22float2(*reinterpret_cast<__half2*>(&q01.x));
    float2 e01 = __half22float2(*reinterpret_cast<__half2*>(&q01.y));
    float2 a10 = __half22float2(*reinterpret_cast<__half2*>(&q10.x));
    float2 e10 = __half22float2(*reinterpret_cast<__half2*>(&q10.y));
    float2 a11 = __half22float2(*reinterpret_cast<__half2*>(&q11.x));
    float2 e11 = __half22float2(*reinterpret_cast<__half2*>(&q11.y));

    float v0 = w00*a00.x + w01*a01.x + w10*a10.x + w11*a11.x;
    float v1 = w00*a00.y + w01*a01.y + w10*a10.y + w11*a11.y;
    float v2 = w00*e00.x + w01*e01.x + w10*e10.x + w11*e11.x;

    int patch = b*1024 + (ir/25)*64 + (ia >> 4);
    __half* so = S + (size_t)patch*KPAD + (ir % 25)*16 + (ia & 15);
    so[0]   = __float2half_rn(v0);
    so[400] = __float2half_rn(v1);
    so[800] = __float2half_rn(v2);
}

// ---------------------------------------------------------------------------
// GEMM (fp16 mma, fp32 accum): C[M][96] = S[M][KPAD] @ Wt[96][KPAD]^T + beff
// BM=128, 256 threads (8 warps: 4M x 2N), BK=32, 4-stage cp.async pipeline.
// Dynamic smem: STAGES * (128*PADH + 96*PADH) halves = 71.7 KB.
// ---------------------------------------------------------------------------
#define AST (128*PADH)           // halves per A stage
#define BST (96*PADH)            // halves per B stage
#define SMEM_BYTES (STAGES*(AST+BST)*2)

__global__ __launch_bounds__(256, 2)
void gemm_f16(const __half* __restrict__ A, const __half* __restrict__ Bw,
              const float* __restrict__ bias, float* __restrict__ C) {
    extern __shared__ __half dsm[];
    __half* As = dsm;                 // [STAGES][128][PADH]
    __half* Bs = dsm + STAGES*AST;    // [STAGES][96][PADH]

    int tid = threadIdx.x;
    int wid = tid >> 5, lane = tid & 31;
    int wm = wid & 3;          // rows wm*32..+31
    int wn = wid >> 2;         // cols wn*48..+47
    int g  = lane >> 2;
    int tg = lane & 3;

    int m0 = blockIdx.x * 128;
    const __half* Ag = A + (size_t)m0 * KPAD;

    uint32_t sA_u = smem_u32(As);
    uint32_t sB_u = smem_u32(Bs);

    // issue one K-tile's cp.asyncs into stage s
    auto issue = [&](int kt, int s) {
        uint32_t abase = sA_u + (uint32_t)s*AST*2;
        uint32_t bbase = sB_u + (uint32_t)s*BST*2;
#pragma unroll
        for (int i = 0; i < 2; i++) {            // A: 512 chunks of 16B
            int e = i*256 + tid, row = e >> 2, c16 = e & 3;
            cp16(abase + (row*PADH + c16*8)*2,
                 Ag + (size_t)row*KPAD + kt*32 + c16*8);
        }
        {                                         // B: 384 chunks
            int e = tid;                          // 0..255
            int row = e >> 2, c16 = e & 3;
            cp16(bbase + (row*PADH + c16*8)*2,
                 Bw + (size_t)row*KPAD + kt*32 + c16*8);
        }
        if (tid < 128) {                          // B chunks 256..383
            int e = 256 + tid;
            int row = e >> 2, c16 = e & 3;
            cp16(bbase + (row*PADH + c16*8)*2,
                 Bw + (size_t)row*KPAD + kt*32 + c16*8);
        }
    };

    float acc[2][6][4];
#pragma unroll
    for (int mt = 0; mt < 2; mt++)
#pragma unroll
        for (int nt = 0; nt < 6; nt++)
#pragma unroll
            for (int q = 0; q < 4; q++) acc[mt][nt][q] = 0.f;

    // prologue: issue tiles 0..STAGES-2
#pragma unroll
    for (int s = 0; s < STAGES-1; s++) { issue(s, s); CP_COMMIT(); }

    for (int kt = 0; kt < NKT; ++kt) {
        CP_WAIT(STAGES-2);
        __syncthreads();

        int nkt = kt + STAGES - 1;
        if (nkt < NKT) issue(nkt, nkt & (STAGES-1));
        CP_COMMIT();

        const __half* Ash = As + (size_t)(kt & (STAGES-1))*AST;
        const __half* Bsh = Bs + (size_t)(kt & (STAGES-1))*BST;

#pragma unroll
        for (int ks = 0; ks < 2; ks++) {         // two k16 steps
            int kb = ks * 16;
            uint32_t af[2][4];
#pragma unroll
            for (int mt = 0; mt < 2; mt++) {
                int rb = wm*32 + mt*16;
                af[mt][0] = *(const uint32_t*)&Ash[(rb + g    )*PADH + kb + 2*tg    ];
                af[mt][1] = *(const uint32_t*)&Ash[(rb + g + 8)*PADH + kb + 2*tg    ];
                af[mt][2] = *(const uint32_t*)&Ash[(rb + g    )*PADH + kb + 2*tg + 8];
                af[mt][3] = *(const uint32_t*)&Ash[(rb + g + 8)*PADH + kb + 2*tg + 8];
            }
            uint32_t bf[6][2];
#pragma unroll
            for (int nt = 0; nt < 6; nt++) {
                int n = wn*48 + nt*8 + g;
                bf[nt][0] = *(const uint32_t*)&Bsh[n*PADH + kb + 2*tg    ];
                bf[nt][1] = *(const uint32_t*)&Bsh[n*PADH + kb + 2*tg + 8];
            }
#pragma unroll
            for (int mt = 0; mt < 2; mt++)
#pragma unroll
                for (int nt = 0; nt < 6; nt++)
                    mma_f16(acc[mt][nt], af[mt][0], af[mt][1], af[mt][2], af[mt][3],
                            bf[nt][0], bf[nt][1]);
        }
        __syncthreads();
    }

    // epilogue: c0=(g,2tg) c1=(g,2tg+1) c2=(g+8,2tg) c3=(g+8,2tg+1)
#pragma unroll
    for (int nt = 0; nt < 6; nt++) {
        int col = wn*48 + nt*8 + 2*tg;
        float2 bv = *(const float2*)(bias + col);
#pragma unroll
        for (int mt = 0; mt < 2; mt++) {
            int row = m0 + wm*32 + mt*16 + g;
            float2 v0 = { acc[mt][nt][0] + bv.x, acc[mt][nt][1] + bv.y };
            float2 v1 = { acc[mt][nt][2] + bv.x, acc[mt][nt][3] + bv.y };
            *(float2*)(C + (size_t)row*96 + col)       = v0;
            *(float2*)(C + (size_t)(row + 8)*96 + col) = v1;
        }
    }
}

// ---------------------------------------------------------------------------
// Launch
// ---------------------------------------------------------------------------
extern "C" void kernel_launch(void* const* d_in, const int* in_sizes, int n_in,
                              void* d_out, int out_size) {
    const float* x    = (const float*)d_in[0];
    const float* dist = (const float*)d_in[1];
    const float* w1   = (const float*)d_in[2];
    const float* b1   = (const float*)d_in[3];
    const float* w2   = (const float*)d_in[4];
    const float* b2   = (const float*)d_in[5];
    float* out = (float*)d_out;

    __half *dS, *dWt;
    uint2* dXh;
    float* dBeff;
    cudaGetSymbolAddress((void**)&dS,    g_S);
    cudaGetSymbolAddress((void**)&dXh,   g_xh);
    cudaGetSymbolAddress((void**)&dWt,   g_Wt);
    cudaGetSymbolAddress((void**)&dBeff, g_beff);

    static bool attr_done = false;
    if (!attr_done) {
        cudaFuncSetAttribute(gemm_f16, cudaFuncAttributeMaxDynamicSharedMemorySize,
                             SMEM_BYTES);
        attr_done = true;
    }

    int nT = MDIM * ED;
    int nTheta = (out_size > nT) ? (out_size - nT) : 0;

    prep_all<<<96, 256>>>(w1, w2, b1, b2, dWt, dBeff, out + nT, nTheta);
    repack_kernel<<<(NB*HPIX + 255)/256, 256>>>(x, dXh, dS);
    sample_kernel<<<(NB*400*1024)/256, 256>>>(dXh, dist, dS);
    gemm_f16<<<MDIM/128, 256, SMEM_BYTES>>>(dS, dWt, dBeff, out);
}

// round 7
// speedup vs baseline: 2.4896x; 1.1765x over previous
#include <cuda_runtime.h>
#include <cuda_fp16.h>
#include <cstdint>

// ---------------------------------------------------------------------------
// Problem constants
// ---------------------------------------------------------------------------
#define NB    32
#define IMGW  224
#define HPIX  (IMGW*IMGW)
#define ED    96
#define KDIM  1200               // 3 * 25 * 16 folded patch size
#define KPAD  1216               // padded to multiple of 32 (zero tail)
#define NKT   (KPAD/32)          // 38 K-tiles of 32
#define MDIM  (NB*16*64)         // 32768 output patches
#define PI_F  3.14159265358979323846f
#define PADH  40                 // smem row pitch in halves (32+8) -> conflict-free
#define STAGES 4

// Scratch (device globals)
__device__ __half g_S[(size_t)MDIM * KPAD];   // sampled fp16, patch-major [M][KPAD]
__device__ uint2  g_xh[(size_t)NB * HPIX];    // repacked image: 4x fp16 (c0,c1,c2,0)
__device__ __half g_Wt[(size_t)ED * KPAD];    // folded weight transposed [c2][KPAD]
__device__ float  g_beff[ED];                 // folded bias (fp32)

// ---------------------------------------------------------------------------
// PTX helpers
// ---------------------------------------------------------------------------
__device__ __forceinline__ void mma_f16(float* c, uint32_t a0, uint32_t a1,
                                        uint32_t a2, uint32_t a3,
                                        uint32_t b0, uint32_t b1) {
    asm volatile(
        "mma.sync.aligned.m16n8k16.row.col.f32.f16.f16.f32 "
        "{%0,%1,%2,%3}, {%4,%5,%6,%7}, {%8,%9}, {%0,%1,%2,%3};"
        : "+f"(c[0]), "+f"(c[1]), "+f"(c[2]), "+f"(c[3])
        : "r"(a0), "r"(a1), "r"(a2), "r"(a3), "r"(b0), "r"(b1));
}
__device__ __forceinline__ uint32_t smem_u32(const void* p) {
    uint32_t a;
    asm("{ .reg .u64 t; cvta.to.shared.u64 t, %1; cvt.u32.u64 %0, t; }" : "=r"(a) : "l"(p));
    return a;
}
__device__ __forceinline__ void cp16(uint32_t dst, const void* src) {
    asm volatile("cp.async.ca.shared.global [%0], [%1], 16;" :: "r"(dst), "l"(src));
}
#define CP_COMMIT()  asm volatile("cp.async.commit_group;" ::: "memory")
#define CP_WAIT(n)   asm volatile("cp.async.wait_group %0;" :: "n"(n) : "memory")
#define LDSM_X4(r0, r1, r2, r3, addr)                                             \
    asm volatile("ldmatrix.sync.aligned.m8n8.x4.shared.b16 {%0,%1,%2,%3}, [%4];"  \
        : "=r"(r0), "=r"(r1), "=r"(r2), "=r"(r3) : "r"(addr))

// ---------------------------------------------------------------------------
// Prep (single kernel): fold weights -> Wt[c2][KPAD] fp16, beff, theta_max.
// ---------------------------------------------------------------------------
__global__ __launch_bounds__(256)
void prep_all(const float* __restrict__ w1, const float* __restrict__ w2,
              const float* __restrict__ b1, const float* __restrict__ b2,
              __half* __restrict__ Wt, float* __restrict__ beff,
              float* __restrict__ outTheta, int nTheta) {
    __shared__ float sw2[96*20];
    __shared__ float sw1[96*60];
    __shared__ float red[96];
    int c2 = blockIdx.x;
    int t  = threadIdx.x;

    for (int i = t; i < 96*20; i += 256) sw2[i] = w2[(size_t)c2*1920 + i];
    for (int i = t; i < 96*60; i += 256) sw1[i] = w1[i];
    __syncthreads();

    for (int k = t; k < KPAD; k += 256) {
        if (k >= KDIM) { Wt[(size_t)c2*KPAD + k] = __float2half(0.f); continue; }
        int c   = k / 400;
        int rem = k - c*400;
        int rr = rem >> 4, aa = rem & 15;
        int i = rr / 5, p = rr - i*5;
        int j = aa >> 2, q = aa & 3;
        int o2 = i*4 + j;
        int o1 = c*20 + p*4 + q;
        float s = 0.f;
#pragma unroll 8
        for (int c1 = 0; c1 < 96; c1++)
            s += sw2[c1*20 + o2] * sw1[c1*60 + o1];
        Wt[(size_t)c2*KPAD + k] = __float2half_rn(s);
    }

    if (t < 96) {
        float s = 0.f;
#pragma unroll
        for (int e = 0; e < 20; e++) s += sw2[t*20 + e];
        red[t] = s * b1[t];
    }
    __syncthreads();
    if (t == 0) {
        float s = b2[c2];
#pragma unroll 8
        for (int i = 0; i < 96; i++) s += red[i];
        beff[c2] = s;
    }
    if (c2 == 0 && t < nTheta) outTheta[t] = 1.5707963267948966f;   // pi/2
}

// ---------------------------------------------------------------------------
// Repack: planar fp32 image -> interleaved fp16x4 (c0,c1,c2,0); zero S tail
// ---------------------------------------------------------------------------
__global__ __launch_bounds__(256)
void repack_kernel(const float* __restrict__ x, uint2* __restrict__ xh,
                   __half* __restrict__ S) {
    int idx = blockIdx.x * 256 + threadIdx.x;
    if (idx < NB*HPIX) {
        int b = idx / HPIX, p = idx - b*HPIX;
        const float* xb = x + (size_t)b*3*HPIX + p;
        float c0 = xb[0], c1 = xb[HPIX], c2 = xb[2*HPIX];
        __half2 lo = __floats2half2_rn(c0, c1);
        __half2 hi = __floats2half2_rn(c2, 0.f);
        uint2 v;
        v.x = *reinterpret_cast<uint32_t*>(&lo);
        v.y = *reinterpret_cast<uint32_t*>(&hi);
        xh[idx] = v;
    }
    if (idx < MDIM*8) {     // zero S cols 1200..1215
        int row = idx >> 3, c = idx & 7;
        uint32_t* Su = reinterpret_cast<uint32_t*>(S);
        Su[((size_t)row*KPAD + 1200)/2 + c] = 0u;
    }
}

// ---------------------------------------------------------------------------
// Sampling: one thread = two adjacent azimuths (same radius -> polynomial
// computed once). 8 LDG.64 + 3 STG.32 per thread. -> S fp16 [M][KPAD]
// ---------------------------------------------------------------------------
__global__ __launch_bounds__(256)
void sample_kernel(const uint2* __restrict__ xh, const float* __restrict__ dist,
                   __half* __restrict__ S) {
    int t = blockIdx.x * blockDim.x + threadIdx.x;   // 32*400*512 threads
    int j  = t & 511;                // azimuth pair index
    int ir = (t >> 9) % 400;
    int b  = t / (400*512);
    int ia0 = 2*j;

    const float* dp = dist + b*4;
    float c0 = 0.2f + dp[0], c1 = 0.2f + dp[1];
    float c2 = 0.2f + dp[2], c3 = 0.2f + dp[3];

    const float tm = PI_F * 0.5f;
    float th  = tm * (ir + 0.5f) * (1.0f/400.0f);
    float t2  = th*th;
    float pn  = th * (c0 + t2*(c1 + t2*(c2 + t2*c3)));
    float tm2 = tm*tm;
    float pd  = tm * (c0 + tm2*(c1 + tm2*(c2 + tm2*c3)));
    float r   = pn / pd * (IMGW * 0.5f);

    const uint2* xb = xh + (size_t)b*HPIX;
    float v[2][3];

#pragma unroll
    for (int s = 0; s < 2; s++) {
        int ia = ia0 + s;
        float phi = 2.0f*PI_F * (ia + 0.5f) * (1.0f/1024.0f);
        float sp, cp;
        __sincosf(phi, &sp, &cp);
        float xc = r*cp, yc = r*sp;

        float gx = (yc * (1.0f/112.0f) + 1.0f) * 0.5f * (IMGW - 1);
        float gy = (xc * (1.0f/112.0f) + 1.0f) * 0.5f * (IMGW - 1);

        float x0f = floorf(gx), y0f = floorf(gy);
        float wx1 = gx - x0f, wx0 = 1.0f - wx1;
        float wy1 = gy - y0f, wy0 = 1.0f - wy1;
        int x0 = min(222, max(0, (int)x0f));
        int y0 = min(222, max(0, (int)y0f));

        float w00 = wx0*wy0, w01 = wx1*wy0, w10 = wx0*wy1, w11 = wx1*wy1;

        const uint2* base = xb + y0*IMGW + x0;
        uint2 q00 = __ldg(base);
        uint2 q01 = __ldg(base + 1);
        uint2 q10 = __ldg(base + IMGW);
        uint2 q11 = __ldg(base + IMGW + 1);

        float2 a00 = __half22float2(*reinterpret_cast<__half2*>(&q00.x));
        float2 e00 = __half22float2(*reinterpret_cast<__half2*>(&q00.y));
        float2 a01 = __half22float2(*reinterpret_cast<__half2*>(&q01.x));
        float2 e01 = __half22float2(*reinterpret_cast<__half2*>(&q01.y));
        float2 a10 = __half22float2(*reinterpret_cast<__half2*>(&q10.x));
        float2 e10 = __half22float2(*reinterpret_cast<__half2*>(&q10.y));
        float2 a11 = __half22float2(*reinterpret_cast<__half2*>(&q11.x));
        float2 e11 = __half22float2(*reinterpret_cast<__half2*>(&q11.y));

        v[s][0] = w00*a00.x + w01*a01.x + w10*a10.x + w11*a11.x;
        v[s][1] = w00*a00.y + w01*a01.y + w10*a10.y + w11*a11.y;
        v[s][2] = w00*e00.x + w01*e01.x + w10*e10.x + w11*e11.x;
    }

    int patch = b*1024 + (ir/25)*64 + (ia0 >> 4);
    int col   = (ir % 25)*16 + (ia0 & 15);        // even -> 4B aligned
    __half* so = S + (size_t)patch*KPAD + col;
#pragma unroll
    for (int ch = 0; ch < 3; ch++)
        *reinterpret_cast<__half2*>(so + ch*400) = __floats2half2_rn(v[0][ch], v[1][ch]);
}

// ---------------------------------------------------------------------------
// GEMM (fp16 mma, fp32 accum): C[M][96] = S[M][KPAD] @ Wt[96][KPAD]^T + beff
// BM=128, 256 threads (8 warps: 4M x 2N), BK=32, 4-stage cp.async pipeline,
// ldmatrix fragment loads, single barrier per K-tile.
// ---------------------------------------------------------------------------
#define AST (128*PADH)           // halves per A stage
#define BST (96*PADH)            // halves per B stage
#define SMEM_BYTES (STAGES*(AST+BST)*2)

__global__ __launch_bounds__(256, 2)
void gemm_f16(const __half* __restrict__ A, const __half* __restrict__ Bw,
              const float* __restrict__ bias, float* __restrict__ C) {
    extern __shared__ __half dsm[];
    __half* As = dsm;                 // [STAGES][128][PADH]
    __half* Bs = dsm + STAGES*AST;    // [STAGES][96][PADH]

    int tid = threadIdx.x;
    int wid = tid >> 5, lane = tid & 31;
    int wm = wid & 3;          // rows wm*32..+31
    int wn = wid >> 2;         // cols wn*48..+47
    int g  = lane >> 2;
    int tg = lane & 3;

    int m0 = blockIdx.x * 128;
    const __half* Ag = A + (size_t)m0 * KPAD;

    uint32_t sA_u = smem_u32(As);
    uint32_t sB_u = smem_u32(Bs);

    // ldmatrix per-thread base offsets (bytes), before stage/kb offsets
    // A x4 (m16,k16): lanes 0-15 -> row rb+(lane&15) @kb; 16-31 -> same row @kb+8
    uint32_t aoff[2];
#pragma unroll
    for (int mt = 0; mt < 2; mt++) {
        int row  = wm*32 + mt*16 + (lane & 15);
        int koff = (lane >> 4) << 3;
        aoff[mt] = (uint32_t)(row*PADH + koff) * 2;
    }
    // B x4 (two n8 tiles): n = nb + (lane&7) + ((lane>>4)<<3); k = kb + (((lane>>3)&1)<<3)
    uint32_t boff[3];
#pragma unroll
    for (int p = 0; p < 3; p++) {
        int n    = wn*48 + p*16 + (lane & 7) + ((lane >> 4) << 3);
        int koff = ((lane >> 3) & 1) << 3;
        boff[p]  = (uint32_t)(n*PADH + koff) * 2;
    }

    // issue one K-tile's cp.asyncs into stage s
    auto issue = [&](int kt, int s) {
        uint32_t abase = sA_u + (uint32_t)s*AST*2;
        uint32_t bbase = sB_u + (uint32_t)s*BST*2;
#pragma unroll
        for (int i = 0; i < 2; i++) {            // A: 512 chunks of 16B
            int e = i*256 + tid, row = e >> 2, c16 = e & 3;
            cp16(abase + (row*PADH + c16*8)*2,
                 Ag + (size_t)row*KPAD + kt*32 + c16*8);
        }
        {
            int e = tid, row = e >> 2, c16 = e & 3;  // B chunks 0..255
            cp16(bbase + (row*PADH + c16*8)*2,
                 Bw + (size_t)row*KPAD + kt*32 + c16*8);
        }
        if (tid < 128) {                          // B chunks 256..383
            int e = 256 + tid, row = e >> 2, c16 = e & 3;
            cp16(bbase + (row*PADH + c16*8)*2,
                 Bw + (size_t)row*KPAD + kt*32 + c16*8);
        }
    };

    float acc[2][6][4];
#pragma unroll
    for (int mt = 0; mt < 2; mt++)
#pragma unroll
        for (int nt = 0; nt < 6; nt++)
#pragma unroll
            for (int q = 0; q < 4; q++) acc[mt][nt][q] = 0.f;

#pragma unroll
    for (int s = 0; s < STAGES-1; s++) { issue(s, s); CP_COMMIT(); }

    for (int kt = 0; kt < NKT; ++kt) {
        CP_WAIT(STAGES-2);
        __syncthreads();   // data visible + stage (kt+3)&3 free for overwrite

        int nkt = kt + STAGES - 1;
        if (nkt < NKT) issue(nkt, nkt & (STAGES-1));
        CP_COMMIT();

        uint32_t abase = sA_u + (uint32_t)(kt & (STAGES-1))*AST*2;
        uint32_t bbase = sB_u + (uint32_t)(kt & (STAGES-1))*BST*2;

#pragma unroll
        for (int ks = 0; ks < 2; ks++) {         // two k16 steps
            uint32_t kb2 = (uint32_t)ks * 32;    // 16 halves = 32 bytes
            uint32_t af[2][4];
#pragma unroll
            for (int mt = 0; mt < 2; mt++)
                LDSM_X4(af[mt][0], af[mt][1], af[mt][2], af[mt][3],
                        abase + aoff[mt] + kb2);
            uint32_t bf[6][2];
#pragma unroll
            for (int p = 0; p < 3; p++)
                LDSM_X4(bf[2*p][0], bf[2*p][1], bf[2*p+1][0], bf[2*p+1][1],
                        bbase + boff[p] + kb2);
#pragma unroll
            for (int mt = 0; mt < 2; mt++)
#pragma unroll
                for (int nt = 0; nt < 6; nt++)
                    mma_f16(acc[mt][nt], af[mt][0], af[mt][1], af[mt][2], af[mt][3],
                            bf[nt][0], bf[nt][1]);
        }
    }

    // epilogue: c0=(g,2tg) c1=(g,2tg+1) c2=(g+8,2tg) c3=(g+8,2tg+1)
#pragma unroll
    for (int nt = 0; nt < 6; nt++) {
        int col = wn*48 + nt*8 + 2*tg;
        float2 bv = *(const float2*)(bias + col);
#pragma unroll
        for (int mt = 0; mt < 2; mt++) {
            int row = m0 + wm*32 + mt*16 + g;
            float2 v0 = { acc[mt][nt][0] + bv.x, acc[mt][nt][1] + bv.y };
            float2 v1 = { acc[mt][nt][2] + bv.x, acc[mt][nt][3] + bv.y };
            *(float2*)(C + (size_t)row*96 + col)       = v0;
            *(float2*)(C + (size_t)(row + 8)*96 + col) = v1;
        }
    }
}

// ---------------------------------------------------------------------------
// Launch
// ---------------------------------------------------------------------------
extern "C" void kernel_launch(void* const* d_in, const int* in_sizes, int n_in,
                              void* d_out, int out_size) {
    const float* x    = (const float*)d_in[0];
    const float* dist = (const float*)d_in[1];
    const float* w1   = (const float*)d_in[2];
    const float* b1   = (const float*)d_in[3];
    const float* w2   = (const float*)d_in[4];
    const float* b2   = (const float*)d_in[5];
    float* out = (float*)d_out;

    __half *dS, *dWt;
    uint2* dXh;
    float* dBeff;
    cudaGetSymbolAddress((void**)&dS,    g_S);
    cudaGetSymbolAddress((void**)&dXh,   g_xh);
    cudaGetSymbolAddress((void**)&dWt,   g_Wt);
    cudaGetSymbolAddress((void**)&dBeff, g_beff);

    static bool attr_done = false;
    if (!attr_done) {
        cudaFuncSetAttribute(gemm_f16, cudaFuncAttributeMaxDynamicSharedMemorySize,
                             SMEM_BYTES);
        attr_done = true;
    }

    int nT = MDIM * ED;
    int nTheta = (out_size > nT) ? (out_size - nT) : 0;

    prep_all<<<96, 256>>>(w1, w2, b1, b2, dWt, dBeff, out + nT, nTheta);
    repack_kernel<<<(NB*HPIX + 255)/256, 256>>>(x, dXh, dS);
    sample_kernel<<<(NB*400*512)/256, 256>>>(dXh, dist, dS);
    gemm_f16<<<MDIM/128, 256, SMEM_BYTES>>>(dS, dWt, dBeff, out);
}